// round 6
// baseline (speedup 1.0000x reference)
#include <cuda_runtime.h>

// Problem constants (fixed by setup_inputs)
namespace {
constexpr int B = 8, C = 64, H = 256, W = 512, SW = 128;
constexpr int HW = H * W;                 // 131072 = 2^17
constexpr int NPTS = B * HW;              // 1048576
constexpr int CPB = SW * SW;              // 16384
constexpr int NCELL = B * CPB;            // 131072
constexpr int NOUT = B * C * CPB;         // 8388608
}

// Scratch (static __device__ arrays — no allocation)
__device__ float g_sphi[H], g_cphi[H], g_sth[W], g_cth[W];
__device__ unsigned int g_maxh_bits;              // orderable-uint of global max valid y
__device__ unsigned long long g_best[NCELL];      // (ord(h)<<32)|idx_in_batch, 0 = empty

// Monotonic float<->uint mapping (preserves full IEEE ordering)
__device__ __forceinline__ unsigned int ford(float f) {
    unsigned int b = __float_as_uint(f);
    return (b & 0x80000000u) ? ~b : (b | 0x80000000u);
}
__device__ __forceinline__ float fdeord(unsigned int u) {
    unsigned int b = (u & 0x80000000u) ? (u & 0x7FFFFFFFu) : ~u;
    return __uint_as_float(b);
}

// Mirror jnp.linspace(0, 2pi, W) / (0, pi, H) in f32:
//   delta = f32(stop)/f32(num-1); out[k] = k*delta; out[num-1] = stop
__global__ void k_tables() {
    int t = threadIdx.x;
    const float TWO_PI = 6.28318530717958647692f;
    const float PI_F   = 3.14159265358979323846f;
    if (t < W) {
        float dth = __fdiv_rn(TWO_PI, 511.0f);
        float th  = (t == W - 1) ? TWO_PI : __fmul_rn((float)t, dth);
        g_sth[t] = sinf(th);
        g_cth[t] = cosf(th);
    }
    if (t < H) {
        float dph = __fdiv_rn(PI_F, 255.0f);
        float ph  = (t == H - 1) ? PI_F : __fmul_rn((float)t, dph);
        g_sphi[t] = sinf(ph);
        g_cphi[t] = cosf(ph);
    }
    if (t == 0) g_maxh_bits = 0u;  // raced inside k_maxy, so init here
}

// Exact f32 op order of the eager XLA graph:
//   X = ((-sinphi)*sintheta)*d ; Y = (-cosphi)*d ; Z = (-(sinphi*costheta))*d
// Returns cell id (or -1 if invalid) and y.
__device__ __forceinline__ int project(int p, float d, float m, float& y) {
    int j = p & (W - 1);
    int i = (p >> 9) & (H - 1);
    int b = p >> 17;
    float sph = __ldg(&g_sphi[i]), cph = __ldg(&g_cphi[i]);
    float sth = __ldg(&g_sth[j]),  cth = __ldg(&g_cth[j]);
    float X = __fmul_rn(__fmul_rn(-sph, sth), d);
    y       = __fmul_rn(-cph, d);
    float Z = __fmul_rn(-__fmul_rn(sph, cth), d);
    float x = truncf(__fdiv_rn(X, m));
    float z = truncf(__fdiv_rn(Z, m));
    bool valid = (x >= -64.0f) && (x <= 63.0f) && (z >= -64.0f) && (z <= 63.0f);
    return valid ? b * CPB + ((int)x + 64) * SW + ((int)z + 64) : -1;
}

// Pass 1: global max of valid y (4 points/thread) + fold g_best zeroing in
// (g_best is not otherwise touched here; the kernel boundary orders it
// before k_key's atomics).
__global__ void k_maxy(const float* __restrict__ depth,
                       const float* __restrict__ mpp) {
    int t = blockIdx.x * blockDim.x + threadIdx.x;  // NPTS/4 = 262144 threads
    if (t < NCELL / 2)
        reinterpret_cast<ulonglong2*>(g_best)[t] = make_ulonglong2(0ull, 0ull);

    int p0 = t * 4;
    float4 d4 = *reinterpret_cast<const float4*>(&depth[p0]);
    float m = __ldg(&mpp[p0 >> 17]);
    unsigned v = 0u;
    float y;
    if (project(p0 + 0, d4.x, m, y) >= 0) v = max(v, ford(y));
    if (project(p0 + 1, d4.y, m, y) >= 0) v = max(v, ford(y));
    if (project(p0 + 2, d4.z, m, y) >= 0) v = max(v, ford(y));
    if (project(p0 + 3, d4.w, m, y) >= 0) v = max(v, ford(y));

    v = __reduce_max_sync(0xFFFFFFFFu, v);
    __shared__ unsigned sm[8];
    int lane = threadIdx.x & 31, wid = threadIdx.x >> 5;
    if (lane == 0) sm[wid] = v;
    __syncthreads();
    if (wid == 0) {
        unsigned u = (lane < (int)(blockDim.x >> 5)) ? sm[lane] : 0u;
        u = __reduce_max_sync(0xFFFFFFFFu, u);
        if (lane == 0 && u) atomicMax(&g_maxh_bits, u);
    }
}

// Pass 2: key = (ord(max_h - y) << 32) | idx; 4 points/thread.
// Intra-thread merge of consecutive equal cells, then match_any + redux
// warp aggregation; group leader issues one read-filtered atomicMax.
// Reproduces lexsort((h, cell)) + keep-last: max h, ties -> max index.
__global__ void k_key(const float* __restrict__ depth,
                      const float* __restrict__ mpp) {
    int t = blockIdx.x * blockDim.x + threadIdx.x;  // NPTS/4 threads
    int p0 = t * 4;
    float4 d4 = *reinterpret_cast<const float4*>(&depth[p0]);
    float m = __ldg(&mpp[p0 >> 17]);
    float maxh = fdeord(g_maxh_bits);

    int cell[4];
    unsigned long long key[4];
    float dv[4] = {d4.x, d4.y, d4.z, d4.w};
    #pragma unroll
    for (int k = 0; k < 4; k++) {
        float y;
        cell[k] = project(p0 + k, dv[k], m, y);
        float h = __fsub_rn(maxh, y);
        key[k] = ((unsigned long long)ford(h) << 32) |
                 (unsigned)((p0 + k) & (HW - 1));
    }
    // Merge consecutive equal cells within the thread (adjacent theta ->
    // frequent duplicates exactly on contended center cells).
    #pragma unroll
    for (int k = 1; k < 4; k++) {
        if (cell[k] == cell[k - 1]) {
            if (key[k - 1] > key[k]) key[k] = key[k - 1];
            cell[k - 1] = -1;
        }
    }

    int lane = threadIdx.x & 31;
    #pragma unroll
    for (int k = 0; k < 4; k++) {
        int c = cell[k];
        unsigned long long kk = (c >= 0) ? key[k] : 0ull;
        // Group lanes by cell (invalid lanes form the c==-1 group, skipped).
        unsigned mask = __match_any_sync(0xFFFFFFFFu, c);
        unsigned hi  = (unsigned)(kk >> 32);
        unsigned mhi = __reduce_max_sync(mask, hi);
        unsigned lo  = (hi == mhi) ? (unsigned)kk : 0u;
        unsigned mlo = __reduce_max_sync(mask, lo);
        if (c >= 0 && lane == __ffs(mask) - 1) {
            unsigned long long gk = ((unsigned long long)mhi << 32) | mlo;
            // Monotonic pre-read filter: stale values are valid lower bounds.
            if (gk > g_best[c]) atomicMax(&g_best[c], gk);
        }
    }
}

// Pass 3: gather winner pixels into [B, C, SW, SW]; empty cell -> 0.
// 8 z-adjacent cells per thread: 64B of best reads, 8 independent scattered
// image loads (MLP=8), two coalesced float4 stores.
__global__ void k_gather(const float* __restrict__ img,
                         float* __restrict__ out) {
    int t = blockIdx.x * blockDim.x + threadIdx.x;  // NOUT/8 threads
    int z8 = t & 15;
    int x  = (t >> 4) & (SW - 1);
    int c  = (t >> 11) & (C - 1);
    int b  = t >> 17;

    const ulonglong2* bp =
        reinterpret_cast<const ulonglong2*>(&g_best[b * CPB + x * SW + z8 * 8]);
    ulonglong2 b0 = bp[0], b1 = bp[1], b2 = bp[2], b3 = bp[3];

    const float* ip = &img[(b * C + c) * HW];
    float v[8] = {0.f, 0.f, 0.f, 0.f, 0.f, 0.f, 0.f, 0.f};
    if (b0.x) v[0] = __ldg(&ip[(unsigned)(b0.x & 0xFFFFFFFFull)]);
    if (b0.y) v[1] = __ldg(&ip[(unsigned)(b0.y & 0xFFFFFFFFull)]);
    if (b1.x) v[2] = __ldg(&ip[(unsigned)(b1.x & 0xFFFFFFFFull)]);
    if (b1.y) v[3] = __ldg(&ip[(unsigned)(b1.y & 0xFFFFFFFFull)]);
    if (b2.x) v[4] = __ldg(&ip[(unsigned)(b2.x & 0xFFFFFFFFull)]);
    if (b2.y) v[5] = __ldg(&ip[(unsigned)(b2.y & 0xFFFFFFFFull)]);
    if (b3.x) v[6] = __ldg(&ip[(unsigned)(b3.x & 0xFFFFFFFFull)]);
    if (b3.y) v[7] = __ldg(&ip[(unsigned)(b3.y & 0xFFFFFFFFull)]);

    float4* op = reinterpret_cast<float4*>(&out[t * 8]);
    op[0] = make_float4(v[0], v[1], v[2], v[3]);
    op[1] = make_float4(v[4], v[5], v[6], v[7]);
}

extern "C" void kernel_launch(void* const* d_in, const int* in_sizes, int n_in,
                              void* d_out, int out_size) {
    const float* img   = (const float*)d_in[0];  // [B,C,H,W]
    const float* depth = (const float*)d_in[1];  // [B,1,H,W]
    const float* mpp   = (const float*)d_in[2];  // [B]
    float* out = (float*)d_out;                  // [B,C,SW,SW]

    k_tables<<<1, 512>>>();
    k_maxy<<<(NPTS / 4) / 256, 256>>>(depth, mpp);
    k_key<<<(NPTS / 4) / 256, 256>>>(depth, mpp);
    k_gather<<<(NOUT / 8) / 256, 256>>>(img, out);
}

// round 7
// speedup vs baseline: 1.2362x; 1.2362x over previous
#include <cuda_runtime.h>

// Problem constants (fixed by setup_inputs)
namespace {
constexpr int B = 8, C = 64, H = 256, W = 512, SW = 128;
constexpr int HW = H * W;                 // 131072 = 2^17
constexpr int NPTS = B * HW;              // 1048576
constexpr int CPB = SW * SW;              // 16384
constexpr int NCELL = B * CPB;            // 131072
constexpr int NOUT = B * C * CPB;         // 8388608
}

// Scratch (static __device__ arrays — no allocation)
__device__ float g_sphi[H], g_cphi[H], g_sth[W], g_cth[W];
__device__ unsigned int g_maxh_bits;              // orderable-uint of global max valid y
__device__ unsigned long long g_best[NCELL];      // (ord(h)<<32)|idx_in_batch, 0 = empty

// Monotonic float<->uint mapping (preserves full IEEE ordering)
__device__ __forceinline__ unsigned int ford(float f) {
    unsigned int b = __float_as_uint(f);
    return (b & 0x80000000u) ? ~b : (b | 0x80000000u);
}
__device__ __forceinline__ float fdeord(unsigned int u) {
    unsigned int b = (u & 0x80000000u) ? (u & 0x7FFFFFFFu) : ~u;
    return __uint_as_float(b);
}

// Init + trig tables in one launch (65536 threads; first 512 do tables).
// Mirror jnp.linspace(0, 2pi, W) / (0, pi, H) in f32:
//   delta = f32(stop)/f32(num-1); out[k] = k*delta; out[num-1] = stop
__global__ void k_init() {
    int t = blockIdx.x * blockDim.x + threadIdx.x;   // NCELL/2 threads
    reinterpret_cast<ulonglong2*>(g_best)[t] = make_ulonglong2(0ull, 0ull);
    const float TWO_PI = 6.28318530717958647692f;
    const float PI_F   = 3.14159265358979323846f;
    if (t < W) {
        float dth = __fdiv_rn(TWO_PI, 511.0f);
        float th  = (t == W - 1) ? TWO_PI : __fmul_rn((float)t, dth);
        g_sth[t] = sinf(th);
        g_cth[t] = cosf(th);
    }
    if (t < H) {
        float dph = __fdiv_rn(PI_F, 255.0f);
        float ph  = (t == H - 1) ? PI_F : __fmul_rn((float)t, dph);
        g_sphi[t] = sinf(ph);
        g_cphi[t] = cosf(ph);
    }
    if (t == 0) g_maxh_bits = 0u;
}

// Exact f32 op order of the eager XLA graph:
//   X = ((-sinphi)*sintheta)*d ; Y = (-cosphi)*d ; Z = (-(sinphi*costheta))*d
// Returns cell id (or -1 if invalid) and y.
__device__ __forceinline__ int project(int p, float d, float m, float& y) {
    int j = p & (W - 1);
    int i = (p >> 9) & (H - 1);
    int b = p >> 17;
    float sph = __ldg(&g_sphi[i]), cph = __ldg(&g_cphi[i]);
    float sth = __ldg(&g_sth[j]),  cth = __ldg(&g_cth[j]);
    float X = __fmul_rn(__fmul_rn(-sph, sth), d);
    y       = __fmul_rn(-cph, d);
    float Z = __fmul_rn(-__fmul_rn(sph, cth), d);
    float x = truncf(__fdiv_rn(X, m));
    float z = truncf(__fdiv_rn(Z, m));
    bool valid = (x >= -64.0f) && (x <= 63.0f) && (z >= -64.0f) && (z <= 63.0f);
    return valid ? b * CPB + ((int)x + 64) * SW + ((int)z + 64) : -1;
}

// Pass 1: global max of valid y. Pure reduction, 4 points per thread (float4).
__global__ void k_maxy(const float* __restrict__ depth,
                       const float* __restrict__ mpp) {
    int t = blockIdx.x * blockDim.x + threadIdx.x;  // NPTS/4 threads
    int p0 = t * 4;
    float4 d4 = *reinterpret_cast<const float4*>(&depth[p0]);
    float m = __ldg(&mpp[p0 >> 17]);
    unsigned v = 0u;
    float y;
    if (project(p0 + 0, d4.x, m, y) >= 0) v = max(v, ford(y));
    if (project(p0 + 1, d4.y, m, y) >= 0) v = max(v, ford(y));
    if (project(p0 + 2, d4.z, m, y) >= 0) v = max(v, ford(y));
    if (project(p0 + 3, d4.w, m, y) >= 0) v = max(v, ford(y));

    v = __reduce_max_sync(0xFFFFFFFFu, v);
    __shared__ unsigned sm[8];
    int lane = threadIdx.x & 31, wid = threadIdx.x >> 5;
    if (lane == 0) sm[wid] = v;
    __syncthreads();
    if (wid == 0) {
        unsigned u = (lane < (int)(blockDim.x >> 5)) ? sm[lane] : 0u;
        u = __reduce_max_sync(0xFFFFFFFFu, u);
        if (lane == 0 && u) atomicMax(&g_maxh_bits, u);
    }
}

// Pass 2 (R5 version, known 14.7us): key = (ord(max_h - y) << 32) | idx;
// warp run-scan aggregation + read-filtered atomicMax per cell.
// Reproduces lexsort((h, cell)) + keep-last: max h, ties -> max index.
__global__ void k_key(const float* __restrict__ depth,
                      const float* __restrict__ mpp) {
    int p = blockIdx.x * blockDim.x + threadIdx.x;
    float d = depth[p];
    float m = __ldg(&mpp[p >> 17]);
    float y;
    int cell = project(p, d, m, y);

    float maxh = fdeord(g_maxh_bits);
    unsigned long long key = 0ull;
    if (cell >= 0) {
        float h = __fsub_rn(maxh, y);
        key = ((unsigned long long)ford(h) << 32) | (unsigned)(p & (HW - 1));
    }

    // Segmented suffix-max over same-cell lane runs (adjacent theta -> long
    // runs exactly on the contended center cells). Leader of each run does
    // one atomic carrying the run max.
    int lane = threadIdx.x & 31;
    #pragma unroll
    for (int dl = 1; dl < 32; dl <<= 1) {
        unsigned long long ok = __shfl_down_sync(0xFFFFFFFFu, key, dl);
        int oc = __shfl_down_sync(0xFFFFFFFFu, cell, dl);
        if (lane + dl < 32 && oc == cell && ok > key) key = ok;
    }
    int pc = __shfl_up_sync(0xFFFFFFFFu, cell, 1);
    bool leader = (lane == 0) || (pc != cell);

    if (leader && cell >= 0) {
        // Monotonic pre-read filter: stale values are valid lower bounds.
        unsigned long long cur = g_best[cell];
        if (key > cur) atomicMax(&g_best[cell], key);
    }
}

// Pass 3: gather winner pixels into [B, C, SW, SW]; empty cell -> 0.
// R5 lane->cell mapping (z4 = lane&31, warp = one x-row) preserved exactly —
// that mapping's per-wavefront sector dedup is what R6 broke. Widen across
// CHANNELS instead: each thread gathers its 4 cells for channels
// c, c+16, c+32, c+48 -> 16 independent scattered loads (MLP=16), 4 coalesced
// float4 stores, best-table reads cut 4x.
__global__ void k_gather(const float* __restrict__ img,
                         float* __restrict__ out) {
    int t = blockIdx.x * blockDim.x + threadIdx.x;  // NOUT/16 threads
    int z4 = t & 31;
    int x  = (t >> 5) & (SW - 1);
    int c0 = (t >> 12) & 15;         // channels c0 + 16*q, q in 0..3
    int b  = t >> 16;

    const unsigned long long* bp = &g_best[b * CPB + x * SW + z4 * 4];
    ulonglong2 b01 = *reinterpret_cast<const ulonglong2*>(bp);
    ulonglong2 b23 = *reinterpret_cast<const ulonglong2*>(bp + 2);
    unsigned r0 = (unsigned)(b01.x & 0xFFFFFFFFull);
    unsigned r1 = (unsigned)(b01.y & 0xFFFFFFFFull);
    unsigned r2 = (unsigned)(b23.x & 0xFFFFFFFFull);
    unsigned r3 = (unsigned)(b23.y & 0xFFFFFFFFull);

    float v[4][4];
    #pragma unroll
    for (int q = 0; q < 4; q++) {
        const float* ip = &img[(b * C + c0 + q * 16) * HW];
        v[q][0] = b01.x ? __ldg(&ip[r0]) : 0.0f;
        v[q][1] = b01.y ? __ldg(&ip[r1]) : 0.0f;
        v[q][2] = b23.x ? __ldg(&ip[r2]) : 0.0f;
        v[q][3] = b23.y ? __ldg(&ip[r3]) : 0.0f;
    }

    #pragma unroll
    for (int q = 0; q < 4; q++) {
        int o = (((b * C + c0 + q * 16) * SW + x) * SW) + z4 * 4;
        *reinterpret_cast<float4*>(&out[o]) =
            make_float4(v[q][0], v[q][1], v[q][2], v[q][3]);
    }
}

extern "C" void kernel_launch(void* const* d_in, const int* in_sizes, int n_in,
                              void* d_out, int out_size) {
    const float* img   = (const float*)d_in[0];  // [B,C,H,W]
    const float* depth = (const float*)d_in[1];  // [B,1,H,W]
    const float* mpp   = (const float*)d_in[2];  // [B]
    float* out = (float*)d_out;                  // [B,C,SW,SW]

    k_init<<<(NCELL / 2) / 256, 256>>>();
    k_maxy<<<(NPTS / 4) / 256, 256>>>(depth, mpp);
    k_key<<<NPTS / 256, 256>>>(depth, mpp);
    k_gather<<<(NOUT / 16) / 256, 256>>>(img, out);
}